// round 6
// baseline (speedup 1.0000x reference)
#include <cuda_runtime.h>
#include <cuda_bf16.h>
#include <math.h>
#include <stdint.h>

// Problem constants
#define BATCH 2
#define SEQ   2048
#define EMB   2048
#define NHEAD 16
#define HDIM  128
#define F3E   6144          // 3*EMB
#define MTOT  (BATCH*SEQ)   // 4096

// ---------------------------------------------------------------------------
// Scratch (device globals; allocation-free)
// ---------------------------------------------------------------------------
__device__ float g_qkv[(size_t)BATCH * SEQ * F3E];   // [B,S,3E] fp32 (GEMM out)

// bf16 hi/lo splits
__device__ __nv_bfloat16 g_xh[(size_t)MTOT * EMB];
__device__ __nv_bfloat16 g_xl[(size_t)MTOT * EMB];
__device__ __nv_bfloat16 g_wqh[(size_t)F3E * EMB];
__device__ __nv_bfloat16 g_wql[(size_t)F3E * EMB];
__device__ __nv_bfloat16 g_owh[(size_t)EMB * EMB];
__device__ __nv_bfloat16 g_owl[(size_t)EMB * EMB];
__device__ __nv_bfloat16 g_ch[(size_t)MTOT * EMB];
__device__ __nv_bfloat16 g_cl[(size_t)MTOT * EMB];

// rope'd q/k and v, pre-split to bf16 hi/lo, layout [B,S,H*D] (stride EMB)
__device__ __nv_bfloat16 g_qh2[(size_t)MTOT * EMB];
__device__ __nv_bfloat16 g_ql2[(size_t)MTOT * EMB];
__device__ __nv_bfloat16 g_kh2[(size_t)MTOT * EMB];
__device__ __nv_bfloat16 g_kl2[(size_t)MTOT * EMB];
__device__ __nv_bfloat16 g_vh2[(size_t)MTOT * EMB];
__device__ __nv_bfloat16 g_vl2[(size_t)MTOT * EMB];

// ---------------------------------------------------------------------------
// helpers
// ---------------------------------------------------------------------------
#define MMA_BF16(d, a, b) \
    asm volatile( \
        "mma.sync.aligned.m16n8k16.row.col.f32.bf16.bf16.f32 " \
        "{%0,%1,%2,%3}, {%4,%5,%6,%7}, {%8,%9}, {%0,%1,%2,%3};" \
        : "+f"((d)[0]), "+f"((d)[1]), "+f"((d)[2]), "+f"((d)[3]) \
        : "r"((a)[0]), "r"((a)[1]), "r"((a)[2]), "r"((a)[3]), \
          "r"((b)[0]), "r"((b)[1]))

#define LDSM4(r, addr) \
    asm volatile("ldmatrix.sync.aligned.m8n8.x4.shared.b16 {%0,%1,%2,%3}, [%4];" \
        : "=r"((r)[0]), "=r"((r)[1]), "=r"((r)[2]), "=r"((r)[3]) : "r"(addr))

#define LDSM4T(r, addr) \
    asm volatile("ldmatrix.sync.aligned.m8n8.x4.trans.shared.b16 {%0,%1,%2,%3}, [%4];" \
        : "=r"((r)[0]), "=r"((r)[1]), "=r"((r)[2]), "=r"((r)[3]) : "r"(addr))

__device__ __forceinline__ uint32_t smem_u32(const void* p) {
    uint32_t a;
    asm("{ .reg .u64 t; cvta.to.shared.u64 t, %1; cvt.u32.u64 %0, t; }"
        : "=r"(a) : "l"(p));
    return a;
}

__device__ __forceinline__ void cp_async16(void* smem_ptr, const void* gptr) {
    uint32_t saddr = smem_u32(smem_ptr);
    asm volatile("cp.async.cg.shared.global [%0], [%1], 16;"
                 :: "r"(saddr), "l"(gptr));
}

__device__ __forceinline__ uint32_t pack_bf16(float a, float b) {
    __nv_bfloat162 t = __float22bfloat162_rn(make_float2(a, b));
    return *(uint32_t*)&t;
}

// ---------------------------------------------------------------------------
// fp32 -> bf16 hi/lo split (vectorized x4)
// ---------------------------------------------------------------------------
__global__ void split_kernel(const float* __restrict__ in,
                             __nv_bfloat16* __restrict__ hi,
                             __nv_bfloat16* __restrict__ lo, int n4)
{
    int i = blockIdx.x * blockDim.x + threadIdx.x;
    if (i >= n4) return;
    float4 v = ((const float4*)in)[i];

    __nv_bfloat16 hx = __float2bfloat16(v.x);
    __nv_bfloat16 hy = __float2bfloat16(v.y);
    __nv_bfloat16 hz = __float2bfloat16(v.z);
    __nv_bfloat16 hw = __float2bfloat16(v.w);
    __nv_bfloat16 lx = __float2bfloat16(v.x - __bfloat162float(hx));
    __nv_bfloat16 ly = __float2bfloat16(v.y - __bfloat162float(hy));
    __nv_bfloat16 lz = __float2bfloat16(v.z - __bfloat162float(hz));
    __nv_bfloat16 lw = __float2bfloat16(v.w - __bfloat162float(hw));

    __nv_bfloat162* hp = (__nv_bfloat162*)(hi + 4 * (size_t)i);
    __nv_bfloat162* lp = (__nv_bfloat162*)(lo + 4 * (size_t)i);
    hp[0] = __halves2bfloat162(hx, hy);
    hp[1] = __halves2bfloat162(hz, hw);
    lp[0] = __halves2bfloat162(lx, ly);
    lp[1] = __halves2bfloat162(lz, lw);
}

// ---------------------------------------------------------------------------
// bf16x3 GEMM via mma.sync + ldmatrix (NT): C = A B^T + bias
// Tile 128x128, K-chunks of 32, 2-stage cp.async, B-fragment reg prefetch.
// ---------------------------------------------------------------------------
#define KC      32
#define TSTR    40
#define TILE_B  (128 * TSTR * 2)
#define STAGE_B (4 * TILE_B)
#define GEMM_SMEM (2 * STAGE_B)

__global__ void __launch_bounds__(256) gemm_mma_bf16x3(
    const __nv_bfloat16* __restrict__ Ah, const __nv_bfloat16* __restrict__ Al,
    const __nv_bfloat16* __restrict__ Bh, const __nv_bfloat16* __restrict__ Bl,
    const float* __restrict__ bias, float* __restrict__ C,
    int M, int N, int K)
{
    extern __shared__ char dsm[];

    const int tid = threadIdx.x;
    const int wid = tid >> 5;
    const int lane = tid & 31;
    const int gid = lane >> 2;
    const int tig = lane & 3;
    const int wm = wid & 3;
    const int wn = wid >> 2;
    const int m0 = blockIdx.y * 128;
    const int n0 = blockIdx.x * 128;

    const int laneA_row  = wm * 32 + (lane & 15);
    const int laneA_ksel = (lane >> 4) * 8;
    const int laneB_row  = wn * 64 + (lane & 7) + ((lane & 16) ? 8 : 0);
    const int laneB_ksel = (lane & 8) ? 8 : 0;

    const uint32_t sb = smem_u32(dsm);

    float acc[2][8][4];
#pragma unroll
    for (int i = 0; i < 2; i++)
#pragma unroll
        for (int j = 0; j < 8; j++)
#pragma unroll
            for (int c = 0; c < 4; c++) acc[i][j][c] = 0.f;

    const int nch = K / KC;

    auto issue = [&](int c, int stage) {
        char* st = dsm + stage * STAGE_B;
        __nv_bfloat16* sAh = (__nv_bfloat16*)(st);
        __nv_bfloat16* sAl = (__nv_bfloat16*)(st + TILE_B);
        __nv_bfloat16* sBh = (__nv_bfloat16*)(st + 2 * TILE_B);
        __nv_bfloat16* sBl = (__nv_bfloat16*)(st + 3 * TILE_B);
        const int k0 = c * KC;
#pragma unroll
        for (int p = 0; p < 2; p++) {
            int id  = tid + p * 256;
            int row = id >> 2;
            int q   = id & 3;
            size_t ga = (size_t)(m0 + row) * K + k0 + q * 8;
            size_t gb = (size_t)(n0 + row) * K + k0 + q * 8;
            int so = row * TSTR + q * 8;
            cp_async16(sAh + so, Ah + ga);
            cp_async16(sAl + so, Al + ga);
            cp_async16(sBh + so, Bh + gb);
            cp_async16(sBl + so, Bl + gb);
        }
        asm volatile("cp.async.commit_group;" ::: "memory");
    };

    issue(0, 0);

    for (int c = 0; c < nch; c++) {
        if (c + 1 < nch) {
            issue(c + 1, (c + 1) & 1);
            asm volatile("cp.async.wait_group 1;" ::: "memory");
        } else {
            asm volatile("cp.async.wait_group 0;" ::: "memory");
        }
        __syncthreads();

        const uint32_t stb = sb + (c & 1) * STAGE_B;

#pragma unroll
        for (int kk = 0; kk < KC; kk += 16) {
            uint32_t ah[2][4], al[2][4];
            uint32_t aA = stb + (uint32_t)((laneA_row * TSTR + kk + laneA_ksel) * 2);
            LDSM4(ah[0], aA);
            LDSM4(ah[1], aA + 16 * TSTR * 2);
            LDSM4(al[0], aA + TILE_B);
            LDSM4(al[1], aA + TILE_B + 16 * TSTR * 2);

            // B-fragment register double buffer
            uint32_t bh4[2][4], bl4[2][4];
            uint32_t bA0 = stb + 2 * TILE_B +
                (uint32_t)((laneB_row * TSTR + kk + laneB_ksel) * 2);
            LDSM4(bh4[0], bA0);
            LDSM4(bl4[0], bA0 + TILE_B);

#pragma unroll
            for (int njp = 0; njp < 4; njp++) {
                const int cur = njp & 1, nxt = cur ^ 1;
                if (njp < 3) {
                    uint32_t bA = stb + 2 * TILE_B +
                        (uint32_t)(((laneB_row + (njp + 1) * 16) * TSTR + kk + laneB_ksel) * 2);
                    LDSM4(bh4[nxt], bA);
                    LDSM4(bl4[nxt], bA + TILE_B);
                }
#pragma unroll
                for (int mi = 0; mi < 2; mi++) {
                    MMA_BF16(acc[mi][2 * njp],     ah[mi], bh4[cur]);
                    MMA_BF16(acc[mi][2 * njp],     ah[mi], bl4[cur]);
                    MMA_BF16(acc[mi][2 * njp],     al[mi], bh4[cur]);
                    MMA_BF16(acc[mi][2 * njp + 1], ah[mi], bh4[cur] + 2);
                    MMA_BF16(acc[mi][2 * njp + 1], ah[mi], bl4[cur] + 2);
                    MMA_BF16(acc[mi][2 * njp + 1], al[mi], bh4[cur] + 2);
                }
            }
        }
        __syncthreads();
    }

#pragma unroll
    for (int mi = 0; mi < 2; mi++) {
        int row = m0 + wm * 32 + mi * 16 + gid;
#pragma unroll
        for (int nj = 0; nj < 8; nj++) {
            int col = n0 + wn * 64 + nj * 8 + tig * 2;
            float2 bv = *(const float2*)(bias + col);
            float2 o0, o1;
            o0.x = acc[mi][nj][0] + bv.x;
            o0.y = acc[mi][nj][1] + bv.y;
            o1.x = acc[mi][nj][2] + bv.x;
            o1.y = acc[mi][nj][3] + bv.y;
            *(float2*)(C + (size_t)row * N + col)       = o0;
            *(float2*)(C + (size_t)(row + 8) * N + col) = o1;
        }
    }
}

// ---------------------------------------------------------------------------
// RoPE + split: read qkv fp32, apply rope to q,k, write q/k/v bf16 hi/lo.
// Output layout [B,S,E] (stride EMB), head-major within row.
// ---------------------------------------------------------------------------
__global__ void rope_split_kernel(
    const float* __restrict__ qkv,
    __nv_bfloat16* __restrict__ qh, __nv_bfloat16* __restrict__ ql,
    __nv_bfloat16* __restrict__ kh, __nv_bfloat16* __restrict__ kl,
    __nv_bfloat16* __restrict__ vh, __nv_bfloat16* __restrict__ vl)
{
    int idx = blockIdx.x * blockDim.x + threadIdx.x;
    if (idx >= BATCH * SEQ * NHEAD * 64) return;
    int i = idx & 63;
    int h = (idx >> 6) & 15;
    int s = (idx >> 10) & 2047;
    int b = idx >> 21;

    double ex  = (double)(2 * i) / 128.0;
    float invf = (float)exp(-ex * 9.210340371976184);
    float ang  = (float)s * invf;
    float sn, cs;
    sincosf(ang, &sn, &cs);

    size_t ibase = ((size_t)(b * SEQ + s)) * F3E + (size_t)h * HDIM;
    const float* q = qkv + ibase;
    const float* k = qkv + ibase + EMB;
    const float* v = qkv + ibase + 2 * EMB;

    float q1 = q[i], q2 = q[i + 64];
    float k1 = k[i], k2 = k[i + 64];
    float v1 = v[i], v2 = v[i + 64];
    float qr1 = q1 * cs - q2 * sn, qr2 = q1 * sn + q2 * cs;
    float kr1 = k1 * cs - k2 * sn, kr2 = k1 * sn + k2 * cs;

    size_t obase = ((size_t)(b * SEQ + s)) * EMB + (size_t)h * HDIM;
#define SPLIT_STORE(arrH, arrL, off, val) do { \
        __nv_bfloat16 _h = __float2bfloat16(val); \
        arrH[obase + (off)] = _h; \
        arrL[obase + (off)] = __float2bfloat16((val) - __bfloat162float(_h)); \
    } while (0)
    SPLIT_STORE(qh, ql, i,      qr1);
    SPLIT_STORE(qh, ql, i + 64, qr2);
    SPLIT_STORE(kh, kl, i,      kr1);
    SPLIT_STORE(kh, kl, i + 64, kr2);
    SPLIT_STORE(vh, vl, i,      v1);
    SPLIT_STORE(vh, vl, i + 64, v2);
#undef SPLIT_STORE
}

// ---------------------------------------------------------------------------
// Flash attention via mma.sync bf16x3 + ldmatrix; inputs pre-split bf16.
// Br=64 (4 warps x 16 rows), Bc=64, D=128. 128 threads.
// smem: Qh/Ql/Kh/Kl/Vh/Vl all [64][136] bf16. Writes ch/cl bf16 hi/lo.
// ---------------------------------------------------------------------------
#define QKS 136
#define OFF_QH 0
#define OFF_QL (64 * QKS)
#define OFF_KH (2 * 64 * QKS)
#define OFF_KL (3 * 64 * QKS)
#define OFF_VH (4 * 64 * QKS)
#define OFF_VL (5 * 64 * QKS)
#define FLASH_SMEM (6 * 64 * QKS * 2)

__global__ void __launch_bounds__(128) flash_mma_kernel(
    const __nv_bfloat16* __restrict__ qh_g, const __nv_bfloat16* __restrict__ ql_g,
    const __nv_bfloat16* __restrict__ kh_g, const __nv_bfloat16* __restrict__ kl_g,
    const __nv_bfloat16* __restrict__ vh_g, const __nv_bfloat16* __restrict__ vl_g,
    __nv_bfloat16* __restrict__ ch_g, __nv_bfloat16* __restrict__ cl_g)
{
    extern __shared__ __nv_bfloat16 fsm[];
    __nv_bfloat16* Qh = fsm + OFF_QH;
    __nv_bfloat16* Ql = fsm + OFF_QL;
    __nv_bfloat16* Kh = fsm + OFF_KH;
    __nv_bfloat16* Kl = fsm + OFF_KL;
    __nv_bfloat16* Vh = fsm + OFF_VH;
    __nv_bfloat16* Vl = fsm + OFF_VL;

    const int tid  = threadIdx.x;
    const int wid  = tid >> 5;
    const int lane = tid & 31;
    const int gid  = lane >> 2;
    const int tig  = lane & 3;
    const int rb = gridDim.x - 1 - blockIdx.x;   // heavy blocks first
    const int h  = blockIdx.y;
    const int b  = blockIdx.z;
    const int r0 = rb * 64;
    const size_t bs = (size_t)b * SEQ;

    const float scale = 0.08838834764831845f;   // 1/sqrt(128)

    // ldmatrix lane selectors
    const int aRow  = wid * 16 + (lane & 15);
    const int aKsel = (lane >> 4) * 8;
    const int bRow  = (lane & 7) + ((lane & 16) ? 8 : 0);
    const int bKsel = (lane & 8) ? 8 : 0;
    const int vTrow = (lane & 7) + ((lane & 8) ? 8 : 0);
    const int vDsel = (lane & 16) ? 8 : 0;

    const uint32_t QhB = smem_u32(Qh);
    const uint32_t QlB = smem_u32(Ql);
    const uint32_t KhB = smem_u32(Kh);
    const uint32_t KlB = smem_u32(Kl);
    const uint32_t VhB = smem_u32(Vh);
    const uint32_t VlB = smem_u32(Vl);

    // Load Q tile (bf16 hi/lo) via cp.async: 64 rows x 16 chunks per array
#pragma unroll
    for (int p = 0; p < 8; p++) {
        int id  = tid + p * 128;       // 0..1023
        int row = id >> 4;
        int c8  = (id & 15) * 8;
        size_t ga = (bs + r0 + row) * EMB + (size_t)h * HDIM + c8;
        cp_async16(&Qh[row * QKS + c8], qh_g + ga);
        cp_async16(&Ql[row * QKS + c8], ql_g + ga);
    }
    asm volatile("cp.async.commit_group;" ::: "memory");

    float m0r = -1e30f, m1r = -1e30f, l0r = 0.f, l1r = 0.f;
    float o[16][4];
#pragma unroll
    for (int na = 0; na < 16; na++)
#pragma unroll
        for (int c = 0; c < 4; c++) o[na][c] = 0.f;

    for (int kblk = 0; kblk <= rb; kblk++) {
        const int c0 = kblk * 64;
        __syncthreads();   // previous iteration done reading K/V

        // Load K and V tiles (bf16 hi/lo) via cp.async
#pragma unroll
        for (int p = 0; p < 8; p++) {
            int id  = tid + p * 128;
            int row = id >> 4;
            int c8  = (id & 15) * 8;
            size_t ga = (bs + c0 + row) * EMB + (size_t)h * HDIM + c8;
            cp_async16(&Kh[row * QKS + c8], kh_g + ga);
            cp_async16(&Kl[row * QKS + c8], kl_g + ga);
            cp_async16(&Vh[row * QKS + c8], vh_g + ga);
            cp_async16(&Vl[row * QKS + c8], vl_g + ga);
        }
        asm volatile("cp.async.commit_group;" ::: "memory");
        asm volatile("cp.async.wait_group 0;" ::: "memory");
        __syncthreads();

        // ---- S = Q K^T (3-term, ldmatrix) ----
        float sc[8][4];
#pragma unroll
        for (int nj = 0; nj < 8; nj++)
#pragma unroll
            for (int c = 0; c < 4; c++) sc[nj][c] = 0.f;

#pragma unroll
        for (int ka = 0; ka < 8; ka++) {
            const int kcol = ka * 16;
            uint32_t ah[4], al[4];
            uint32_t aAddr = QhB + (uint32_t)((aRow * QKS + kcol + aKsel) * 2);
            LDSM4(ah, aAddr);
            LDSM4(al, aAddr + (QlB - QhB));
#pragma unroll
            for (int njp = 0; njp < 4; njp++) {
                uint32_t bAddr = KhB +
                    (uint32_t)(((njp * 16 + bRow) * QKS + kcol + bKsel) * 2);
                uint32_t bh4[4], bl4[4];
                LDSM4(bh4, bAddr);
                LDSM4(bl4, bAddr + (KlB - KhB));
                MMA_BF16(sc[2 * njp],     ah, bh4);
                MMA_BF16(sc[2 * njp],     ah, bl4);
                MMA_BF16(sc[2 * njp],     al, bh4);
                MMA_BF16(sc[2 * njp + 1], ah, bh4 + 2);
                MMA_BF16(sc[2 * njp + 1], ah, bl4 + 2);
                MMA_BF16(sc[2 * njp + 1], al, bh4 + 2);
            }
        }

        // ---- scale + causal mask ----
        const bool diag = (kblk == rb);
        const int grow0 = r0 + wid * 16 + gid;
#pragma unroll
        for (int nj = 0; nj < 8; nj++) {
            int col = c0 + nj * 8 + 2 * tig;
            sc[nj][0] *= scale; sc[nj][1] *= scale;
            sc[nj][2] *= scale; sc[nj][3] *= scale;
            if (diag) {
                if (col     > grow0)     sc[nj][0] = -1e30f;
                if (col + 1 > grow0)     sc[nj][1] = -1e30f;
                if (col     > grow0 + 8) sc[nj][2] = -1e30f;
                if (col + 1 > grow0 + 8) sc[nj][3] = -1e30f;
            }
        }

        // ---- online softmax ----
        float mx0 = -1e30f, mx1 = -1e30f;
#pragma unroll
        for (int nj = 0; nj < 8; nj++) {
            mx0 = fmaxf(mx0, fmaxf(sc[nj][0], sc[nj][1]));
            mx1 = fmaxf(mx1, fmaxf(sc[nj][2], sc[nj][3]));
        }
        mx0 = fmaxf(mx0, __shfl_xor_sync(0xffffffffu, mx0, 1));
        mx0 = fmaxf(mx0, __shfl_xor_sync(0xffffffffu, mx0, 2));
        mx1 = fmaxf(mx1, __shfl_xor_sync(0xffffffffu, mx1, 1));
        mx1 = fmaxf(mx1, __shfl_xor_sync(0xffffffffu, mx1, 2));

        float mn0 = fmaxf(m0r, mx0);
        float mn1 = fmaxf(m1r, mx1);
        float al0 = __expf(m0r - mn0);
        float al1 = __expf(m1r - mn1);

        float s0 = 0.f, s1 = 0.f;
#pragma unroll
        for (int nj = 0; nj < 8; nj++) {
            sc[nj][0] = __expf(sc[nj][0] - mn0);
            sc[nj][1] = __expf(sc[nj][1] - mn0);
            sc[nj][2] = __expf(sc[nj][2] - mn1);
            sc[nj][3] = __expf(sc[nj][3] - mn1);
            s0 += sc[nj][0] + sc[nj][1];
            s1 += sc[nj][2] + sc[nj][3];
        }
        s0 += __shfl_xor_sync(0xffffffffu, s0, 1);
        s0 += __shfl_xor_sync(0xffffffffu, s0, 2);
        s1 += __shfl_xor_sync(0xffffffffu, s1, 1);
        s1 += __shfl_xor_sync(0xffffffffu, s1, 2);

        l0r = l0r * al0 + s0;
        l1r = l1r * al1 + s1;
        m0r = mn0; m1r = mn1;

#pragma unroll
        for (int na = 0; na < 16; na++) {
            o[na][0] *= al0; o[na][1] *= al0;
            o[na][2] *= al1; o[na][3] *= al1;
        }

        // ---- O += P V (3-term; P from regs, V via ldmatrix.trans) ----
#pragma unroll
        for (int ka2 = 0; ka2 < 4; ka2++) {
            const int j0 = 2 * ka2, j1 = 2 * ka2 + 1;
            uint32_t aph[4], apl[4];
            {
                float p0 = sc[j0][0], p1 = sc[j0][1];
                float p2 = sc[j0][2], p3 = sc[j0][3];
                float q0 = sc[j1][0], q1 = sc[j1][1];
                float q2 = sc[j1][2], q3 = sc[j1][3];
                aph[0] = pack_bf16(p0, p1);
                aph[1] = pack_bf16(p2, p3);
                aph[2] = pack_bf16(q0, q1);
                aph[3] = pack_bf16(q2, q3);
                __nv_bfloat162 t0 = *(__nv_bfloat162*)&aph[0];
                __nv_bfloat162 t1 = *(__nv_bfloat162*)&aph[1];
                __nv_bfloat162 t2 = *(__nv_bfloat162*)&aph[2];
                __nv_bfloat162 t3 = *(__nv_bfloat162*)&aph[3];
                apl[0] = pack_bf16(p0 - __bfloat162float(t0.x), p1 - __bfloat162float(t0.y));
                apl[1] = pack_bf16(p2 - __bfloat162float(t1.x), p3 - __bfloat162float(t1.y));
                apl[2] = pack_bf16(q0 - __bfloat162float(t2.x), q1 - __bfloat162float(t2.y));
                apl[3] = pack_bf16(q2 - __bfloat162float(t3.x), q3 - __bfloat162float(t3.y));
            }
            const int t0row = ka2 * 16;
#pragma unroll
            for (int nap = 0; nap < 8; nap++) {
                uint32_t vAddr = VhB +
                    (uint32_t)(((t0row + vTrow) * QKS + nap * 16 + vDsel) * 2);
                uint32_t bh4[4], bl4[4];
                LDSM4T(bh4, vAddr);
                LDSM4T(bl4, vAddr + (VlB - VhB));
                MMA_BF16(o[2 * nap],     aph, bh4);
                MMA_BF16(o[2 * nap],     aph, bl4);
                MMA_BF16(o[2 * nap],     apl, bh4);
                MMA_BF16(o[2 * nap + 1], aph, bh4 + 2);
                MMA_BF16(o[2 * nap + 1], aph, bl4 + 2);
                MMA_BF16(o[2 * nap + 1], apl, bh4 + 2);
            }
        }
    }

    // ---- epilogue: normalize, split to bf16 hi/lo, write ch/cl ----
    float inv0 = 1.f / l0r;
    float inv1 = 1.f / l1r;
    int row = r0 + wid * 16 + gid;
    size_t ob0 = (bs + row) * EMB + (size_t)h * HDIM;
    size_t ob1 = (bs + row + 8) * EMB + (size_t)h * HDIM;
#pragma unroll
    for (int na = 0; na < 16; na++) {
        int col = na * 8 + 2 * tig;
        float f0 = o[na][0] * inv0, f1 = o[na][1] * inv0;
        float f2 = o[na][2] * inv1, f3 = o[na][3] * inv1;
        uint32_t h01 = pack_bf16(f0, f1);
        uint32_t h23 = pack_bf16(f2, f3);
        __nv_bfloat162 th0 = *(__nv_bfloat162*)&h01;
        __nv_bfloat162 th1 = *(__nv_bfloat162*)&h23;
        uint32_t l01 = pack_bf16(f0 - __bfloat162float(th0.x), f1 - __bfloat162float(th0.y));
        uint32_t l23 = pack_bf16(f2 - __bfloat162float(th1.x), f3 - __bfloat162float(th1.y));
        *(uint32_t*)(ch_g + ob0 + col) = h01;
        *(uint32_t*)(cl_g + ob0 + col) = l01;
        *(uint32_t*)(ch_g + ob1 + col) = h23;
        *(uint32_t*)(cl_g + ob1 + col) = l23;
    }
}

// ---------------------------------------------------------------------------
// Launch
// ---------------------------------------------------------------------------
extern "C" void kernel_launch(void* const* d_in, const int* in_sizes, int n_in,
                              void* d_out, int out_size)
{
    const float* x      = (const float*)d_in[0];
    const float* wqkv_w = (const float*)d_in[1];
    const float* wqkv_b = (const float*)d_in[2];
    const float* out_w  = (const float*)d_in[3];
    const float* out_b  = (const float*)d_in[4];
    float* out = (float*)d_out;

    float *qkv;
    __nv_bfloat16 *xh, *xl, *wqh, *wql, *owh, *owl, *ch, *cl;
    __nv_bfloat16 *qh2, *ql2, *kh2, *kl2, *vh2, *vl2;
    cudaGetSymbolAddress((void**)&qkv, g_qkv);
    cudaGetSymbolAddress((void**)&xh, g_xh);
    cudaGetSymbolAddress((void**)&xl, g_xl);
    cudaGetSymbolAddress((void**)&wqh, g_wqh);
    cudaGetSymbolAddress((void**)&wql, g_wql);
    cudaGetSymbolAddress((void**)&owh, g_owh);
    cudaGetSymbolAddress((void**)&owl, g_owl);
    cudaGetSymbolAddress((void**)&ch, g_ch);
    cudaGetSymbolAddress((void**)&cl, g_cl);
    cudaGetSymbolAddress((void**)&qh2, g_qh2);
    cudaGetSymbolAddress((void**)&ql2, g_ql2);
    cudaGetSymbolAddress((void**)&kh2, g_kh2);
    cudaGetSymbolAddress((void**)&kl2, g_kl2);
    cudaGetSymbolAddress((void**)&vh2, g_vh2);
    cudaGetSymbolAddress((void**)&vl2, g_vl2);

    cudaFuncSetAttribute(gemm_mma_bf16x3,
                         cudaFuncAttributeMaxDynamicSharedMemorySize, GEMM_SMEM);
    cudaFuncSetAttribute(flash_mma_kernel,
                         cudaFuncAttributeMaxDynamicSharedMemorySize, FLASH_SMEM);

    // 0) Split inputs to bf16 hi/lo
    {
        int n4 = (MTOT * EMB) / 4;
        split_kernel<<<(n4 + 255) / 256, 256>>>(x, xh, xl, n4);
    }
    {
        int n4 = (F3E * EMB) / 4;
        split_kernel<<<(n4 + 255) / 256, 256>>>(wqkv_w, wqh, wql, n4);
    }
    {
        int n4 = (EMB * EMB) / 4;
        split_kernel<<<(n4 + 255) / 256, 256>>>(out_w, owh, owl, n4);
    }

    // 1) QKV projection: [4096,2048] x [6144,2048]^T
    gemm_mma_bf16x3<<<dim3(F3E / 128, MTOT / 128), 256, GEMM_SMEM>>>(
        xh, xl, wqh, wql, wqkv_b, qkv, MTOT, F3E, EMB);

    // 2) RoPE + split q/k/v to bf16 hi/lo
    rope_split_kernel<<<(BATCH * SEQ * NHEAD * 64) / 256, 256>>>(
        qkv, qh2, ql2, kh2, kl2, vh2, vl2);

    // 3) Causal flash attention (bf16 in, bf16 hi/lo out)
    flash_mma_kernel<<<dim3(SEQ / 64, NHEAD, BATCH), 128, FLASH_SMEM>>>(
        qh2, ql2, kh2, kl2, vh2, vl2, ch, cl);

    // 4) Output projection
    gemm_mma_bf16x3<<<dim3(EMB / 128, MTOT / 128), 256, GEMM_SMEM>>>(
        ch, cl, owh, owl, out_b, out, MTOT, EMB, EMB);
}

// round 7
// speedup vs baseline: 1.1527x; 1.1527x over previous
#include <cuda_runtime.h>
#include <cuda_bf16.h>
#include <math.h>
#include <stdint.h>

// Problem constants
#define BATCH 2
#define SEQ   2048
#define EMB   2048
#define NHEAD 16
#define HDIM  128
#define F3E   6144          // 3*EMB
#define MTOT  (BATCH*SEQ)   // 4096

// ---------------------------------------------------------------------------
// Scratch (device globals; allocation-free)
// ---------------------------------------------------------------------------
__device__ float g_qkv[(size_t)BATCH * SEQ * F3E];   // [B,S,3E] fp32 (GEMM out)

// bf16 hi/lo splits
__device__ __nv_bfloat16 g_xh[(size_t)MTOT * EMB];
__device__ __nv_bfloat16 g_xl[(size_t)MTOT * EMB];
__device__ __nv_bfloat16 g_wqh[(size_t)F3E * EMB];
__device__ __nv_bfloat16 g_wql[(size_t)F3E * EMB];
__device__ __nv_bfloat16 g_owh[(size_t)EMB * EMB];
__device__ __nv_bfloat16 g_owl[(size_t)EMB * EMB];
__device__ __nv_bfloat16 g_ch[(size_t)MTOT * EMB];
__device__ __nv_bfloat16 g_cl[(size_t)MTOT * EMB];

// rope'd q/k and v, pre-split to bf16 hi/lo, layout [B,S,H*D] (stride EMB)
__device__ __nv_bfloat16 g_qh2[(size_t)MTOT * EMB];
__device__ __nv_bfloat16 g_ql2[(size_t)MTOT * EMB];
__device__ __nv_bfloat16 g_kh2[(size_t)MTOT * EMB];
__device__ __nv_bfloat16 g_kl2[(size_t)MTOT * EMB];
__device__ __nv_bfloat16 g_vh2[(size_t)MTOT * EMB];
__device__ __nv_bfloat16 g_vl2[(size_t)MTOT * EMB];

// ---------------------------------------------------------------------------
// helpers
// ---------------------------------------------------------------------------
#define MMA_BF16(d, a, b) \
    asm volatile( \
        "mma.sync.aligned.m16n8k16.row.col.f32.bf16.bf16.f32 " \
        "{%0,%1,%2,%3}, {%4,%5,%6,%7}, {%8,%9}, {%0,%1,%2,%3};" \
        : "+f"((d)[0]), "+f"((d)[1]), "+f"((d)[2]), "+f"((d)[3]) \
        : "r"((a)[0]), "r"((a)[1]), "r"((a)[2]), "r"((a)[3]), \
          "r"((b)[0]), "r"((b)[1]))

#define LDSM4(r, addr) \
    asm volatile("ldmatrix.sync.aligned.m8n8.x4.shared.b16 {%0,%1,%2,%3}, [%4];" \
        : "=r"((r)[0]), "=r"((r)[1]), "=r"((r)[2]), "=r"((r)[3]) : "r"(addr))

#define LDSM4T(r, addr) \
    asm volatile("ldmatrix.sync.aligned.m8n8.x4.trans.shared.b16 {%0,%1,%2,%3}, [%4];" \
        : "=r"((r)[0]), "=r"((r)[1]), "=r"((r)[2]), "=r"((r)[3]) : "r"(addr))

__device__ __forceinline__ uint32_t smem_u32(const void* p) {
    uint32_t a;
    asm("{ .reg .u64 t; cvta.to.shared.u64 t, %1; cvt.u32.u64 %0, t; }"
        : "=r"(a) : "l"(p));
    return a;
}

__device__ __forceinline__ void cp_async16(void* smem_ptr, const void* gptr) {
    uint32_t saddr = smem_u32(smem_ptr);
    asm volatile("cp.async.cg.shared.global [%0], [%1], 16;"
                 :: "r"(saddr), "l"(gptr));
}

__device__ __forceinline__ uint32_t pack_bf16(float a, float b) {
    __nv_bfloat162 t = __float22bfloat162_rn(make_float2(a, b));
    return *(uint32_t*)&t;
}

// ---------------------------------------------------------------------------
// fp32 -> bf16 hi/lo split (vectorized x4)
// ---------------------------------------------------------------------------
__global__ void split_kernel(const float* __restrict__ in,
                             __nv_bfloat16* __restrict__ hi,
                             __nv_bfloat16* __restrict__ lo, int n4)
{
    int i = blockIdx.x * blockDim.x + threadIdx.x;
    if (i >= n4) return;
    float4 v = ((const float4*)in)[i];

    __nv_bfloat16 hx = __float2bfloat16(v.x);
    __nv_bfloat16 hy = __float2bfloat16(v.y);
    __nv_bfloat16 hz = __float2bfloat16(v.z);
    __nv_bfloat16 hw = __float2bfloat16(v.w);
    __nv_bfloat16 lx = __float2bfloat16(v.x - __bfloat162float(hx));
    __nv_bfloat16 ly = __float2bfloat16(v.y - __bfloat162float(hy));
    __nv_bfloat16 lz = __float2bfloat16(v.z - __bfloat162float(hz));
    __nv_bfloat16 lw = __float2bfloat16(v.w - __bfloat162float(hw));

    __nv_bfloat162* hp = (__nv_bfloat162*)(hi + 4 * (size_t)i);
    __nv_bfloat162* lp = (__nv_bfloat162*)(lo + 4 * (size_t)i);
    hp[0] = __halves2bfloat162(hx, hy);
    hp[1] = __halves2bfloat162(hz, hw);
    lp[0] = __halves2bfloat162(lx, ly);
    lp[1] = __halves2bfloat162(lz, lw);
}

// ---------------------------------------------------------------------------
// bf16x3 GEMM via mma.sync + ldmatrix (NT): C = A B^T + bias
// Tile 128x128, K-chunks of 32, 2-stage cp.async pipeline.
// EXACT R5 inner loop; __launch_bounds__(256,2) pins regs <=128 (2 CTAs/SM).
// ---------------------------------------------------------------------------
#define KC      32
#define TSTR    40
#define TILE_B  (128 * TSTR * 2)
#define STAGE_B (4 * TILE_B)
#define GEMM_SMEM (2 * STAGE_B)

__global__ void __launch_bounds__(256, 2) gemm_mma_bf16x3(
    const __nv_bfloat16* __restrict__ Ah, const __nv_bfloat16* __restrict__ Al,
    const __nv_bfloat16* __restrict__ Bh, const __nv_bfloat16* __restrict__ Bl,
    const float* __restrict__ bias, float* __restrict__ C,
    int M, int N, int K)
{
    extern __shared__ char dsm[];

    const int tid = threadIdx.x;
    const int wid = tid >> 5;
    const int lane = tid & 31;
    const int gid = lane >> 2;
    const int tig = lane & 3;
    const int wm = wid & 3;
    const int wn = wid >> 2;
    const int m0 = blockIdx.y * 128;
    const int n0 = blockIdx.x * 128;

    const int laneA_row  = wm * 32 + (lane & 15);
    const int laneA_ksel = (lane >> 4) * 8;
    const int laneB_row  = wn * 64 + (lane & 7) + ((lane & 16) ? 8 : 0);
    const int laneB_ksel = (lane & 8) ? 8 : 0;

    const uint32_t sb = smem_u32(dsm);

    float acc[2][8][4];
#pragma unroll
    for (int i = 0; i < 2; i++)
#pragma unroll
        for (int j = 0; j < 8; j++)
#pragma unroll
            for (int c = 0; c < 4; c++) acc[i][j][c] = 0.f;

    const int nch = K / KC;

    auto issue = [&](int c, int stage) {
        char* st = dsm + stage * STAGE_B;
        __nv_bfloat16* sAh = (__nv_bfloat16*)(st);
        __nv_bfloat16* sAl = (__nv_bfloat16*)(st + TILE_B);
        __nv_bfloat16* sBh = (__nv_bfloat16*)(st + 2 * TILE_B);
        __nv_bfloat16* sBl = (__nv_bfloat16*)(st + 3 * TILE_B);
        const int k0 = c * KC;
#pragma unroll
        for (int p = 0; p < 2; p++) {
            int id  = tid + p * 256;
            int row = id >> 2;
            int q   = id & 3;
            size_t ga = (size_t)(m0 + row) * K + k0 + q * 8;
            size_t gb = (size_t)(n0 + row) * K + k0 + q * 8;
            int so = row * TSTR + q * 8;
            cp_async16(sAh + so, Ah + ga);
            cp_async16(sAl + so, Al + ga);
            cp_async16(sBh + so, Bh + gb);
            cp_async16(sBl + so, Bl + gb);
        }
        asm volatile("cp.async.commit_group;" ::: "memory");
    };

    issue(0, 0);

    for (int c = 0; c < nch; c++) {
        if (c + 1 < nch) {
            issue(c + 1, (c + 1) & 1);
            asm volatile("cp.async.wait_group 1;" ::: "memory");
        } else {
            asm volatile("cp.async.wait_group 0;" ::: "memory");
        }
        __syncthreads();

        const uint32_t stb = sb + (c & 1) * STAGE_B;

#pragma unroll
        for (int kk = 0; kk < KC; kk += 16) {
            uint32_t ah[2][4], al[2][4];
            uint32_t aA = stb + (uint32_t)((laneA_row * TSTR + kk + laneA_ksel) * 2);
            LDSM4(ah[0], aA);
            LDSM4(ah[1], aA + 16 * TSTR * 2);
            LDSM4(al[0], aA + TILE_B);
            LDSM4(al[1], aA + TILE_B + 16 * TSTR * 2);

#pragma unroll
            for (int njp = 0; njp < 4; njp++) {
                uint32_t bA = stb + 2 * TILE_B +
                    (uint32_t)(((laneB_row + njp * 16) * TSTR + kk + laneB_ksel) * 2);
                uint32_t bh4[4], bl4[4];
                LDSM4(bh4, bA);
                LDSM4(bl4, bA + TILE_B);
#pragma unroll
                for (int mi = 0; mi < 2; mi++) {
                    MMA_BF16(acc[mi][2 * njp],     ah[mi], bh4);
                    MMA_BF16(acc[mi][2 * njp],     ah[mi], bl4);
                    MMA_BF16(acc[mi][2 * njp],     al[mi], bh4);
                    MMA_BF16(acc[mi][2 * njp + 1], ah[mi], bh4 + 2);
                    MMA_BF16(acc[mi][2 * njp + 1], ah[mi], bl4 + 2);
                    MMA_BF16(acc[mi][2 * njp + 1], al[mi], bh4 + 2);
                }
            }
        }
        __syncthreads();
    }

#pragma unroll
    for (int mi = 0; mi < 2; mi++) {
        int row = m0 + wm * 32 + mi * 16 + gid;
#pragma unroll
        for (int nj = 0; nj < 8; nj++) {
            int col = n0 + wn * 64 + nj * 8 + tig * 2;
            float2 bv = *(const float2*)(bias + col);
            float2 o0, o1;
            o0.x = acc[mi][nj][0] + bv.x;
            o0.y = acc[mi][nj][1] + bv.y;
            o1.x = acc[mi][nj][2] + bv.x;
            o1.y = acc[mi][nj][3] + bv.y;
            *(float2*)(C + (size_t)row * N + col)       = o0;
            *(float2*)(C + (size_t)(row + 8) * N + col) = o1;
        }
    }
}

// ---------------------------------------------------------------------------
// RoPE + split: read qkv fp32, apply rope to q,k, write q/k/v bf16 hi/lo.
// ---------------------------------------------------------------------------
__global__ void rope_split_kernel(
    const float* __restrict__ qkv,
    __nv_bfloat16* __restrict__ qh, __nv_bfloat16* __restrict__ ql,
    __nv_bfloat16* __restrict__ kh, __nv_bfloat16* __restrict__ kl,
    __nv_bfloat16* __restrict__ vh, __nv_bfloat16* __restrict__ vl)
{
    int idx = blockIdx.x * blockDim.x + threadIdx.x;
    if (idx >= BATCH * SEQ * NHEAD * 64) return;
    int i = idx & 63;
    int h = (idx >> 6) & 15;
    int s = (idx >> 10) & 2047;
    int b = idx >> 21;

    double ex  = (double)(2 * i) / 128.0;
    float invf = (float)exp(-ex * 9.210340371976184);
    float ang  = (float)s * invf;
    float sn, cs;
    sincosf(ang, &sn, &cs);

    size_t ibase = ((size_t)(b * SEQ + s)) * F3E + (size_t)h * HDIM;
    const float* q = qkv + ibase;
    const float* k = qkv + ibase + EMB;
    const float* v = qkv + ibase + 2 * EMB;

    float q1 = q[i], q2 = q[i + 64];
    float k1 = k[i], k2 = k[i + 64];
    float v1 = v[i], v2 = v[i + 64];
    float qr1 = q1 * cs - q2 * sn, qr2 = q1 * sn + q2 * cs;
    float kr1 = k1 * cs - k2 * sn, kr2 = k1 * sn + k2 * cs;

    size_t obase = ((size_t)(b * SEQ + s)) * EMB + (size_t)h * HDIM;
#define SPLIT_STORE(arrH, arrL, off, val) do { \
        __nv_bfloat16 _h = __float2bfloat16(val); \
        arrH[obase + (off)] = _h; \
        arrL[obase + (off)] = __float2bfloat16((val) - __bfloat162float(_h)); \
    } while (0)
    SPLIT_STORE(qh, ql, i,      qr1);
    SPLIT_STORE(qh, ql, i + 64, qr2);
    SPLIT_STORE(kh, kl, i,      kr1);
    SPLIT_STORE(kh, kl, i + 64, kr2);
    SPLIT_STORE(vh, vl, i,      v1);
    SPLIT_STORE(vh, vl, i + 64, v2);
#undef SPLIT_STORE
}

// ---------------------------------------------------------------------------
// Flash attention via mma.sync bf16x3 + ldmatrix; inputs pre-split bf16.
// Br=64 (4 warps x 16 rows), Bc=64, D=128. 128 threads.
// ---------------------------------------------------------------------------
#define QKS 136
#define OFF_QH 0
#define OFF_QL (64 * QKS)
#define OFF_KH (2 * 64 * QKS)
#define OFF_KL (3 * 64 * QKS)
#define OFF_VH (4 * 64 * QKS)
#define OFF_VL (5 * 64 * QKS)
#define FLASH_SMEM (6 * 64 * QKS * 2)

__global__ void __launch_bounds__(128) flash_mma_kernel(
    const __nv_bfloat16* __restrict__ qh_g, const __nv_bfloat16* __restrict__ ql_g,
    const __nv_bfloat16* __restrict__ kh_g, const __nv_bfloat16* __restrict__ kl_g,
    const __nv_bfloat16* __restrict__ vh_g, const __nv_bfloat16* __restrict__ vl_g,
    __nv_bfloat16* __restrict__ ch_g, __nv_bfloat16* __restrict__ cl_g)
{
    extern __shared__ __nv_bfloat16 fsm[];
    __nv_bfloat16* Qh = fsm + OFF_QH;
    __nv_bfloat16* Ql = fsm + OFF_QL;
    __nv_bfloat16* Kh = fsm + OFF_KH;
    __nv_bfloat16* Kl = fsm + OFF_KL;
    __nv_bfloat16* Vh = fsm + OFF_VH;
    __nv_bfloat16* Vl = fsm + OFF_VL;

    const int tid  = threadIdx.x;
    const int wid  = tid >> 5;
    const int lane = tid & 31;
    const int gid  = lane >> 2;
    const int tig  = lane & 3;
    const int rb = gridDim.x - 1 - blockIdx.x;   // heavy blocks first
    const int h  = blockIdx.y;
    const int b  = blockIdx.z;
    const int r0 = rb * 64;
    const size_t bs = (size_t)b * SEQ;

    const float scale = 0.08838834764831845f;   // 1/sqrt(128)

    const int aRow  = wid * 16 + (lane & 15);
    const int aKsel = (lane >> 4) * 8;
    const int bRow  = (lane & 7) + ((lane & 16) ? 8 : 0);
    const int bKsel = (lane & 8) ? 8 : 0;
    const int vTrow = (lane & 7) + ((lane & 8) ? 8 : 0);
    const int vDsel = (lane & 16) ? 8 : 0;

    const uint32_t QhB = smem_u32(Qh);
    const uint32_t QlB = smem_u32(Ql);
    const uint32_t KhB = smem_u32(Kh);
    const uint32_t KlB = smem_u32(Kl);
    const uint32_t VhB = smem_u32(Vh);
    const uint32_t VlB = smem_u32(Vl);

    // Load Q tile (bf16 hi/lo) via cp.async
#pragma unroll
    for (int p = 0; p < 8; p++) {
        int id  = tid + p * 128;
        int row = id >> 4;
        int c8  = (id & 15) * 8;
        size_t ga = (bs + r0 + row) * EMB + (size_t)h * HDIM + c8;
        cp_async16(&Qh[row * QKS + c8], qh_g + ga);
        cp_async16(&Ql[row * QKS + c8], ql_g + ga);
    }
    asm volatile("cp.async.commit_group;" ::: "memory");

    float m0r = -1e30f, m1r = -1e30f, l0r = 0.f, l1r = 0.f;
    float o[16][4];
#pragma unroll
    for (int na = 0; na < 16; na++)
#pragma unroll
        for (int c = 0; c < 4; c++) o[na][c] = 0.f;

    for (int kblk = 0; kblk <= rb; kblk++) {
        const int c0 = kblk * 64;
        __syncthreads();

        // Load K and V tiles (bf16 hi/lo) via cp.async
#pragma unroll
        for (int p = 0; p < 8; p++) {
            int id  = tid + p * 128;
            int row = id >> 4;
            int c8  = (id & 15) * 8;
            size_t ga = (bs + c0 + row) * EMB + (size_t)h * HDIM + c8;
            cp_async16(&Kh[row * QKS + c8], kh_g + ga);
            cp_async16(&Kl[row * QKS + c8], kl_g + ga);
            cp_async16(&Vh[row * QKS + c8], vh_g + ga);
            cp_async16(&Vl[row * QKS + c8], vl_g + ga);
        }
        asm volatile("cp.async.commit_group;" ::: "memory");
        asm volatile("cp.async.wait_group 0;" ::: "memory");
        __syncthreads();

        // ---- S = Q K^T (3-term, ldmatrix) ----
        float sc[8][4];
#pragma unroll
        for (int nj = 0; nj < 8; nj++)
#pragma unroll
            for (int c = 0; c < 4; c++) sc[nj][c] = 0.f;

#pragma unroll
        for (int ka = 0; ka < 8; ka++) {
            const int kcol = ka * 16;
            uint32_t ah[4], al[4];
            uint32_t aAddr = QhB + (uint32_t)((aRow * QKS + kcol + aKsel) * 2);
            LDSM4(ah, aAddr);
            LDSM4(al, aAddr + (QlB - QhB));
#pragma unroll
            for (int njp = 0; njp < 4; njp++) {
                uint32_t bAddr = KhB +
                    (uint32_t)(((njp * 16 + bRow) * QKS + kcol + bKsel) * 2);
                uint32_t bh4[4], bl4[4];
                LDSM4(bh4, bAddr);
                LDSM4(bl4, bAddr + (KlB - KhB));
                MMA_BF16(sc[2 * njp],     ah, bh4);
                MMA_BF16(sc[2 * njp],     ah, bl4);
                MMA_BF16(sc[2 * njp],     al, bh4);
                MMA_BF16(sc[2 * njp + 1], ah, bh4 + 2);
                MMA_BF16(sc[2 * njp + 1], ah, bl4 + 2);
                MMA_BF16(sc[2 * njp + 1], al, bh4 + 2);
            }
        }

        // ---- scale + causal mask ----
        const bool diag = (kblk == rb);
        const int grow0 = r0 + wid * 16 + gid;
#pragma unroll
        for (int nj = 0; nj < 8; nj++) {
            int col = c0 + nj * 8 + 2 * tig;
            sc[nj][0] *= scale; sc[nj][1] *= scale;
            sc[nj][2] *= scale; sc[nj][3] *= scale;
            if (diag) {
                if (col     > grow0)     sc[nj][0] = -1e30f;
                if (col + 1 > grow0)     sc[nj][1] = -1e30f;
                if (col     > grow0 + 8) sc[nj][2] = -1e30f;
                if (col + 1 > grow0 + 8) sc[nj][3] = -1e30f;
            }
        }

        // ---- online softmax ----
        float mx0 = -1e30f, mx1 = -1e30f;
#pragma unroll
        for (int nj = 0; nj < 8; nj++) {
            mx0 = fmaxf(mx0, fmaxf(sc[nj][0], sc[nj][1]));
            mx1 = fmaxf(mx1, fmaxf(sc[nj][2], sc[nj][3]));
        }
        mx0 = fmaxf(mx0, __shfl_xor_sync(0xffffffffu, mx0, 1));
        mx0 = fmaxf(mx0, __shfl_xor_sync(0xffffffffu, mx0, 2));
        mx1 = fmaxf(mx1, __shfl_xor_sync(0xffffffffu, mx1, 1));
        mx1 = fmaxf(mx1, __shfl_xor_sync(0xffffffffu, mx1, 2));

        float mn0 = fmaxf(m0r, mx0);
        float mn1 = fmaxf(m1r, mx1);
        float al0 = __expf(m0r - mn0);
        float al1 = __expf(m1r - mn1);

        float s0 = 0.f, s1 = 0.f;
#pragma unroll
        for (int nj = 0; nj < 8; nj++) {
            sc[nj][0] = __expf(sc[nj][0] - mn0);
            sc[nj][1] = __expf(sc[nj][1] - mn0);
            sc[nj][2] = __expf(sc[nj][2] - mn1);
            sc[nj][3] = __expf(sc[nj][3] - mn1);
            s0 += sc[nj][0] + sc[nj][1];
            s1 += sc[nj][2] + sc[nj][3];
        }
        s0 += __shfl_xor_sync(0xffffffffu, s0, 1);
        s0 += __shfl_xor_sync(0xffffffffu, s0, 2);
        s1 += __shfl_xor_sync(0xffffffffu, s1, 1);
        s1 += __shfl_xor_sync(0xffffffffu, s1, 2);

        l0r = l0r * al0 + s0;
        l1r = l1r * al1 + s1;
        m0r = mn0; m1r = mn1;

#pragma unroll
        for (int na = 0; na < 16; na++) {
            o[na][0] *= al0; o[na][1] *= al0;
            o[na][2] *= al1; o[na][3] *= al1;
        }

        // ---- O += P V (3-term; P from regs, V via ldmatrix.trans) ----
#pragma unroll
        for (int ka2 = 0; ka2 < 4; ka2++) {
            const int j0 = 2 * ka2, j1 = 2 * ka2 + 1;
            uint32_t aph[4], apl[4];
            {
                float p0 = sc[j0][0], p1 = sc[j0][1];
                float p2 = sc[j0][2], p3 = sc[j0][3];
                float q0 = sc[j1][0], q1 = sc[j1][1];
                float q2 = sc[j1][2], q3 = sc[j1][3];
                aph[0] = pack_bf16(p0, p1);
                aph[1] = pack_bf16(p2, p3);
                aph[2] = pack_bf16(q0, q1);
                aph[3] = pack_bf16(q2, q3);
                __nv_bfloat162 t0 = *(__nv_bfloat162*)&aph[0];
                __nv_bfloat162 t1 = *(__nv_bfloat162*)&aph[1];
                __nv_bfloat162 t2 = *(__nv_bfloat162*)&aph[2];
                __nv_bfloat162 t3 = *(__nv_bfloat162*)&aph[3];
                apl[0] = pack_bf16(p0 - __bfloat162float(t0.x), p1 - __bfloat162float(t0.y));
                apl[1] = pack_bf16(p2 - __bfloat162float(t1.x), p3 - __bfloat162float(t1.y));
                apl[2] = pack_bf16(q0 - __bfloat162float(t2.x), q1 - __bfloat162float(t2.y));
                apl[3] = pack_bf16(q2 - __bfloat162float(t3.x), q3 - __bfloat162float(t3.y));
            }
            const int t0row = ka2 * 16;
#pragma unroll
            for (int nap = 0; nap < 8; nap++) {
                uint32_t vAddr = VhB +
                    (uint32_t)(((t0row + vTrow) * QKS + nap * 16 + vDsel) * 2);
                uint32_t bh4[4], bl4[4];
                LDSM4T(bh4, vAddr);
                LDSM4T(bl4, vAddr + (VlB - VhB));
                MMA_BF16(o[2 * nap],     aph, bh4);
                MMA_BF16(o[2 * nap],     aph, bl4);
                MMA_BF16(o[2 * nap],     apl, bh4);
                MMA_BF16(o[2 * nap + 1], aph, bh4 + 2);
                MMA_BF16(o[2 * nap + 1], aph, bl4 + 2);
                MMA_BF16(o[2 * nap + 1], apl, bh4 + 2);
            }
        }
    }

    // ---- epilogue: normalize, split to bf16 hi/lo, write ch/cl ----
    float inv0 = 1.f / l0r;
    float inv1 = 1.f / l1r;
    int row = r0 + wid * 16 + gid;
    size_t ob0 = (bs + row) * EMB + (size_t)h * HDIM;
    size_t ob1 = (bs + row + 8) * EMB + (size_t)h * HDIM;
#pragma unroll
    for (int na = 0; na < 16; na++) {
        int col = na * 8 + 2 * tig;
        float f0 = o[na][0] * inv0, f1 = o[na][1] * inv0;
        float f2 = o[na][2] * inv1, f3 = o[na][3] * inv1;
        uint32_t h01 = pack_bf16(f0, f1);
        uint32_t h23 = pack_bf16(f2, f3);
        __nv_bfloat162 th0 = *(__nv_bfloat162*)&h01;
        __nv_bfloat162 th1 = *(__nv_bfloat162*)&h23;
        uint32_t l01 = pack_bf16(f0 - __bfloat162float(th0.x), f1 - __bfloat162float(th0.y));
        uint32_t l23 = pack_bf16(f2 - __bfloat162float(th1.x), f3 - __bfloat162float(th1.y));
        *(uint32_t*)(ch_g + ob0 + col) = h01;
        *(uint32_t*)(cl_g + ob0 + col) = l01;
        *(uint32_t*)(ch_g + ob1 + col) = h23;
        *(uint32_t*)(cl_g + ob1 + col) = l23;
    }
}

// ---------------------------------------------------------------------------
// Launch
// ---------------------------------------------------------------------------
extern "C" void kernel_launch(void* const* d_in, const int* in_sizes, int n_in,
                              void* d_out, int out_size)
{
    const float* x      = (const float*)d_in[0];
    const float* wqkv_w = (const float*)d_in[1];
    const float* wqkv_b = (const float*)d_in[2];
    const float* out_w  = (const float*)d_in[3];
    const float* out_b  = (const float*)d_in[4];
    float* out = (float*)d_out;

    float *qkv;
    __nv_bfloat16 *xh, *xl, *wqh, *wql, *owh, *owl, *ch, *cl;
    __nv_bfloat16 *qh2, *ql2, *kh2, *kl2, *vh2, *vl2;
    cudaGetSymbolAddress((void**)&qkv, g_qkv);
    cudaGetSymbolAddress((void**)&xh, g_xh);
    cudaGetSymbolAddress((void**)&xl, g_xl);
    cudaGetSymbolAddress((void**)&wqh, g_wqh);
    cudaGetSymbolAddress((void**)&wql, g_wql);
    cudaGetSymbolAddress((void**)&owh, g_owh);
    cudaGetSymbolAddress((void**)&owl, g_owl);
    cudaGetSymbolAddress((void**)&ch, g_ch);
    cudaGetSymbolAddress((void**)&cl, g_cl);
    cudaGetSymbolAddress((void**)&qh2, g_qh2);
    cudaGetSymbolAddress((void**)&ql2, g_ql2);
    cudaGetSymbolAddress((void**)&kh2, g_kh2);
    cudaGetSymbolAddress((void**)&kl2, g_kl2);
    cudaGetSymbolAddress((void**)&vh2, g_vh2);
    cudaGetSymbolAddress((void**)&vl2, g_vl2);

    cudaFuncSetAttribute(gemm_mma_bf16x3,
                         cudaFuncAttributeMaxDynamicSharedMemorySize, GEMM_SMEM);
    cudaFuncSetAttribute(flash_mma_kernel,
                         cudaFuncAttributeMaxDynamicSharedMemorySize, FLASH_SMEM);

    // 0) Split inputs to bf16 hi/lo
    {
        int n4 = (MTOT * EMB) / 4;
        split_kernel<<<(n4 + 255) / 256, 256>>>(x, xh, xl, n4);
    }
    {
        int n4 = (F3E * EMB) / 4;
        split_kernel<<<(n4 + 255) / 256, 256>>>(wqkv_w, wqh, wql, n4);
    }
    {
        int n4 = (EMB * EMB) / 4;
        split_kernel<<<(n4 + 255) / 256, 256>>>(out_w, owh, owl, n4);
    }

    // 1) QKV projection: [4096,2048] x [6144,2048]^T
    gemm_mma_bf16x3<<<dim3(F3E / 128, MTOT / 128), 256, GEMM_SMEM>>>(
        xh, xl, wqh, wql, wqkv_b, qkv, MTOT, F3E, EMB);

    // 2) RoPE + split q/k/v to bf16 hi/lo
    rope_split_kernel<<<(BATCH * SEQ * NHEAD * 64) / 256, 256>>>(
        qkv, qh2, ql2, kh2, kl2, vh2, vl2);

    // 3) Causal flash attention (bf16 in, bf16 hi/lo out)
    flash_mma_kernel<<<dim3(SEQ / 64, NHEAD, BATCH), 128, FLASH_SMEM>>>(
        qh2, ql2, kh2, kl2, vh2, vl2, ch, cl);

    // 4) Output projection
    gemm_mma_bf16x3<<<dim3(EMB / 128, MTOT / 128), 256, GEMM_SMEM>>>(
        ch, cl, owh, owl, out_b, out, MTOT, EMB, EMB);
}